// round 2
// baseline (speedup 1.0000x reference)
#include <cuda_runtime.h>
#include <cuda_pipeline.h>

typedef unsigned long long u64;

#define BB 2
#define CC 256
#define RR 32
#define NN 6272
#define NT 49      // NN / 128
#define JS 3       // split-KV factor

// ---------------- scratch (device globals; allocation is forbidden) --------
__device__ float g_q [BB][RR][NN];      // pre-scaled by (1/sqrt(32))*log2(e)
__device__ float g_k [BB][RR][NN];
__device__ float g_vt[BB][NN][RR];      // v transposed: [n][r]
__device__ float g_op[BB*JS][RR][NN];   // unnormalized split partials
__device__ float g_mm[BB*JS][NN];
__device__ float g_ll[BB*JS][NN];

// ---------------- f32x2 helpers (sm_103a packed fp32) ----------------------
__device__ __forceinline__ u64 pack2(float a, float b) {
    u64 r; asm("mov.b64 %0,{%1,%2};" : "=l"(r) : "f"(a), "f"(b)); return r;
}
__device__ __forceinline__ u64 dup2(float a) {
    u64 r; asm("mov.b64 %0,{%1,%1};" : "=l"(r) : "f"(a)); return r;
}
__device__ __forceinline__ u64 ffma2(u64 a, u64 b, u64 c) {
    u64 d; asm("fma.rn.f32x2 %0,%1,%2,%3;" : "=l"(d) : "l"(a), "l"(b), "l"(c)); return d;
}
__device__ __forceinline__ u64 fmul2(u64 a, u64 b) {
    u64 d; asm("mul.rn.f32x2 %0,%1,%2;" : "=l"(d) : "l"(a), "l"(b)); return d;
}
__device__ __forceinline__ void unpack2(u64 a, float& x, float& y) {
    asm("mov.b64 {%0,%1},%2;" : "=f"(x), "=f"(y) : "l"(a));
}
__device__ __forceinline__ float ex2(float x) {
    float y; asm("ex2.approx.f32 %0,%1;" : "=f"(y) : "f"(x)); return y;
}

// ============================================================================
// Kernel 1: QKV projection (1x1x1 conv == channel GEMM). grid (49, 3, 2)
// ============================================================================
__global__ void __launch_bounds__(256) proj_kernel(
    const float* __restrict__ x,
    const float* __restrict__ qw,
    const float* __restrict__ kw,
    const float* __restrict__ vw)
{
    __shared__ float xs[64 * 128];   // [cc][nn]
    __shared__ float ws[32 * 64];    // [r][cc]
    int tid   = threadIdx.x;
    int nt    = blockIdx.x;
    int which = blockIdx.y;
    int b     = blockIdx.z;
    const float* w  = (which == 0) ? qw : (which == 1) ? kw : vw;
    const float* xb = x + (size_t)b * CC * NN + nt * 128;

    int tr = tid >> 5;      // 0..7  -> r0 = tr*4
    int tn = tid & 31;      // n0 = tn*4
    u64 acc[4][2];
    #pragma unroll
    for (int i = 0; i < 4; i++) { acc[i][0] = 0ull; acc[i][1] = 0ull; }

    for (int c0 = 0; c0 < CC; c0 += 64) {
        #pragma unroll
        for (int i = 0; i < 8; i++) {
            int lin4 = tid + i * 256;              // 0..2047
            int cc = lin4 >> 5, nn4 = (lin4 & 31) * 4;
            *(float4*)&xs[cc * 128 + nn4] =
                *(const float4*)&xb[(size_t)(c0 + cc) * NN + nn4];
        }
        #pragma unroll
        for (int i = 0; i < 2; i++) {
            int lin4 = tid + i * 256;              // 0..511
            int r = lin4 >> 4, cc4 = (lin4 & 15) * 4;
            *(float4*)&ws[r * 64 + cc4] = *(const float4*)&w[r * 256 + c0 + cc4];
        }
        __syncthreads();
        #pragma unroll 8
        for (int cc = 0; cc < 64; cc++) {
            float4 xv = *(float4*)&xs[cc * 128 + tn * 4];
            u64 x01 = pack2(xv.x, xv.y), x23 = pack2(xv.z, xv.w);
            #pragma unroll
            for (int rr = 0; rr < 4; rr++) {
                u64 wv = dup2(ws[(tr * 4 + rr) * 64 + cc]);
                acc[rr][0] = ffma2(wv, x01, acc[rr][0]);
                acc[rr][1] = ffma2(wv, x23, acc[rr][1]);
            }
        }
        __syncthreads();
    }

    const float qscale = 0.17677669529663687f * 1.4426950408889634f; // 1/sqrt(32)*log2(e)
    #pragma unroll
    for (int rr = 0; rr < 4; rr++) {
        float a, bv, c2, d2;
        unpack2(acc[rr][0], a, bv);
        unpack2(acc[rr][1], c2, d2);
        int r = tr * 4 + rr;
        int n = nt * 128 + tn * 4;
        if (which == 0) {
            *(float4*)&g_q[b][r][n] =
                make_float4(a * qscale, bv * qscale, c2 * qscale, d2 * qscale);
        } else if (which == 1) {
            *(float4*)&g_k[b][r][n] = make_float4(a, bv, c2, d2);
        } else {
            g_vt[b][n + 0][r] = a;  g_vt[b][n + 1][r] = bv;
            g_vt[b][n + 2][r] = c2; g_vt[b][n + 3][r] = d2;
        }
    }
}

// ============================================================================
// Kernel 2: flash attention with split-KV. grid (49, 3, 2), 256 threads
// smem: qs[32*128] | ks 2x[32*128] | vs 2x[128*32] | pT[128*132]
// ============================================================================
#define FL_SMEM_FLOATS (4096 + 8192 + 8192 + 128 * 132)   // 37376
#define FL_SMEM_BYTES  (FL_SMEM_FLOATS * 4)               // 149504

__device__ __forceinline__ void load_kv(float* ks, float* vs, int buf,
                                        int b, int j0, int tid)
{
    float* kd = ks + buf * 4096;
    float* vd = vs + buf * 4096;
    const float* kg = &g_k[b][0][0];
    #pragma unroll
    for (int i = 0; i < 4; i++) {
        int lin4 = tid + i * 256;               // 0..1023
        int r = lin4 >> 5, jj4 = (lin4 & 31) * 4;
        __pipeline_memcpy_async(&kd[r * 128 + jj4], &kg[(size_t)r * NN + j0 + jj4], 16);
    }
    const float* vg = &g_vt[b][j0][0];
    #pragma unroll
    for (int i = 0; i < 4; i++) {
        int lin4 = tid + i * 256;
        __pipeline_memcpy_async(&vd[lin4 * 4], &vg[lin4 * 4], 16);
    }
    __pipeline_commit();
}

__global__ void __launch_bounds__(256) flash_kernel()
{
    extern __shared__ float sm[];
    float* qs = sm;                 // [32][128]
    float* ks = sm + 4096;          // 2 x [32][128]
    float* vs = sm + 12288;         // 2 x [128][32]
    float* pT = sm + 20480;         // [128][132]

    int tid = threadIdx.x;
    int it  = blockIdx.x;
    int spl = blockIdx.y;
    int b   = blockIdx.z;
    int i0  = it * 128;
    int jt0 = (spl == 0) ? 0 : (17 + (spl - 1) * 16);
    int njt = (spl == 0) ? 17 : 16;

    int ti = tid >> 4, tj = tid & 15;
    int io = ti * 8;                // query offset within tile (8 rows)
    int jo = tj * 8;                // key offset within tile (S stage)
    int r2 = tj * 2;                // r pair owned in PV stage

    // load Q tile
    #pragma unroll
    for (int i = 0; i < 4; i++) {
        int lin4 = tid + i * 256;
        int r = lin4 >> 5, ii4 = (lin4 & 31) * 4;
        *(float4*)&qs[r * 128 + ii4] = *(const float4*)&g_q[b][r][i0 + ii4];
    }

    u64 o01[4][2];                  // [(i pair a)][r2 + rb], pairs over i
    #pragma unroll
    for (int a = 0; a < 4; a++) { o01[a][0] = 0ull; o01[a][1] = 0ull; }
    float m[8], l[8];
    #pragma unroll
    for (int ii = 0; ii < 8; ii++) { m[ii] = -1e30f; l[ii] = 0.0f; }

    load_kv(ks, vs, 0, b, jt0 * 128, tid);   // prefetch tile 0

    for (int jt = 0; jt < njt; jt++) {
        int buf = jt & 1;
        __pipeline_wait_prior(0);
        __syncthreads();            // kv buf ready; all PV reads of jt-1 done
        if (jt + 1 < njt) load_kv(ks, vs, (jt + 1) & 1, b, (jt0 + jt + 1) * 128, tid);

        float* kb = ks + buf * 4096;
        float* vb = vs + buf * 4096;

        // ---- S = Q^T K : 8i x 8j register tile, f32x2 over j pairs --------
        u64 sp2[8][4];
        #pragma unroll
        for (int ii = 0; ii < 8; ii++)
            #pragma unroll
            for (int jj = 0; jj < 4; jj++) sp2[ii][jj] = 0ull;

        #pragma unroll 8
        for (int r = 0; r < 32; r++) {
            float4 qa = *(float4*)&qs[r * 128 + io];
            float4 qb = *(float4*)&qs[r * 128 + io + 4];
            float4 ka = *(float4*)&kb[r * 128 + jo];
            float4 kc = *(float4*)&kb[r * 128 + jo + 4];
            u64 k01 = pack2(ka.x, ka.y), k23 = pack2(ka.z, ka.w);
            u64 k45 = pack2(kc.x, kc.y), k67 = pack2(kc.z, kc.w);
            float qv[8] = {qa.x, qa.y, qa.z, qa.w, qb.x, qb.y, qb.z, qb.w};
            #pragma unroll
            for (int ii = 0; ii < 8; ii++) {
                u64 qd = dup2(qv[ii]);
                sp2[ii][0] = ffma2(qd, k01, sp2[ii][0]);
                sp2[ii][1] = ffma2(qd, k23, sp2[ii][1]);
                sp2[ii][2] = ffma2(qd, k45, sp2[ii][2]);
                sp2[ii][3] = ffma2(qd, k67, sp2[ii][3]);
            }
        }

        // ---- online softmax; write exp(P) transposed to smem --------------
        float pcr[8];
        #pragma unroll
        for (int ii = 0; ii < 8; ii++) {
            float a0,a1,a2,a3,a4,a5,a6,a7;
            unpack2(sp2[ii][0], a0, a1);
            unpack2(sp2[ii][1], a2, a3);
            unpack2(sp2[ii][2], a4, a5);
            unpack2(sp2[ii][3], a6, a7);
            float tm = fmaxf(fmaxf(fmaxf(a0,a1), fmaxf(a2,a3)),
                             fmaxf(fmaxf(a4,a5), fmaxf(a6,a7)));
            tm = fmaxf(tm, __shfl_xor_sync(0xffffffffu, tm, 1));
            tm = fmaxf(tm, __shfl_xor_sync(0xffffffffu, tm, 2));
            tm = fmaxf(tm, __shfl_xor_sync(0xffffffffu, tm, 4));
            tm = fmaxf(tm, __shfl_xor_sync(0xffffffffu, tm, 8));
            float mn = fmaxf(m[ii], tm);
            float cr = ex2(m[ii] - mn);
            pcr[ii] = cr;
            m[ii] = mn;
            float p0 = ex2(a0 - mn), p1 = ex2(a1 - mn);
            float p2 = ex2(a2 - mn), p3 = ex2(a3 - mn);
            float p4 = ex2(a4 - mn), p5 = ex2(a5 - mn);
            float p6 = ex2(a6 - mn), p7 = ex2(a7 - mn);
            l[ii] = l[ii] * cr + ((p0+p1)+(p2+p3)) + ((p4+p5)+(p6+p7));
            pT[(jo + 0) * 132 + io + ii] = p0;
            pT[(jo + 1) * 132 + io + ii] = p1;
            pT[(jo + 2) * 132 + io + ii] = p2;
            pT[(jo + 3) * 132 + io + ii] = p3;
            pT[(jo + 4) * 132 + io + ii] = p4;
            pT[(jo + 5) * 132 + io + ii] = p5;
            pT[(jo + 6) * 132 + io + ii] = p6;
            pT[(jo + 7) * 132 + io + ii] = p7;
        }
        // rescale O accumulators (per-i corrections, packed in i pairs)
        #pragma unroll
        for (int a = 0; a < 4; a++) {
            u64 cp = pack2(pcr[2*a], pcr[2*a+1]);
            o01[a][0] = fmul2(o01[a][0], cp);
            o01[a][1] = fmul2(o01[a][1], cp);
        }
        __syncthreads();            // pT complete

        // ---- PV: o[i][r] += P[i][j] * vt[j][r] -----------------------------
        #pragma unroll 4
        for (int j = 0; j < 128; j++) {
            float2 vv = *(float2*)&vb[j * 32 + r2];
            u64 v0 = dup2(vv.x), v1 = dup2(vv.y);
            float4 pa = *(float4*)&pT[j * 132 + io];
            float4 pb = *(float4*)&pT[j * 132 + io + 4];
            u64 p01 = pack2(pa.x, pa.y), p23 = pack2(pa.z, pa.w);
            u64 p45 = pack2(pb.x, pb.y), p67 = pack2(pb.z, pb.w);
            o01[0][0] = ffma2(p01, v0, o01[0][0]);
            o01[0][1] = ffma2(p01, v1, o01[0][1]);
            o01[1][0] = ffma2(p23, v0, o01[1][0]);
            o01[1][1] = ffma2(p23, v1, o01[1][1]);
            o01[2][0] = ffma2(p45, v0, o01[2][0]);
            o01[2][1] = ffma2(p45, v1, o01[2][1]);
            o01[3][0] = ffma2(p67, v0, o01[3][0]);
            o01[3][1] = ffma2(p67, v1, o01[3][1]);
        }
        // next iteration's top __syncthreads separates PV reads from pT writes
    }

    // ---- store unnormalized partials + row stats ---------------------------
    int bs = b * JS + spl;
    #pragma unroll
    for (int a = 0; a < 4; a++) {
        float x0, x1, y0, y1;
        unpack2(o01[a][0], x0, x1);    // (i=2a,2a+1) at r2
        unpack2(o01[a][1], y0, y1);    // (i=2a,2a+1) at r2+1
        g_op[bs][r2    ][i0 + io + 2*a    ] = x0;
        g_op[bs][r2    ][i0 + io + 2*a + 1] = x1;
        g_op[bs][r2 + 1][i0 + io + 2*a    ] = y0;
        g_op[bs][r2 + 1][i0 + io + 2*a + 1] = y1;
    }
    #pragma unroll
    for (int ii = 0; ii < 8; ii++) {
        float lv = l[ii];
        lv += __shfl_xor_sync(0xffffffffu, lv, 1);
        lv += __shfl_xor_sync(0xffffffffu, lv, 2);
        lv += __shfl_xor_sync(0xffffffffu, lv, 4);
        lv += __shfl_xor_sync(0xffffffffu, lv, 8);
        if (tj == 0) {
            g_mm[bs][i0 + io + ii] = m[ii];
            g_ll[bs][i0 + io + ii] = lv;
        }
    }
}

// ============================================================================
// Kernel 3: split combine + output projection + residual. grid (49, 2)
// smem: oc[32*128] | ows[256*32] | wsc[3*128] | os[256*128]
// ============================================================================
#define K3_SMEM_FLOATS (4096 + 8192 + 384 + 32768)   // 45440
#define K3_SMEM_BYTES  (K3_SMEM_FLOATS * 4)          // 181760

__global__ void __launch_bounds__(256) combine_kernel(
    const float* __restrict__ x,
    const float* __restrict__ ow,
    float* __restrict__ out)
{
    extern __shared__ float sm[];
    float* oc  = sm;            // [32][128] normalized combined O
    float* ows = sm + 4096;     // [256][32]
    float* wsc = sm + 12288;    // [3][128]  (split weight * 1/l)
    float* os  = sm + 12672;    // [256][128]

    int tid = threadIdx.x;
    int nt  = blockIdx.x;
    int b   = blockIdx.y;
    int n0  = nt * 128;

    #pragma unroll
    for (int i = 0; i < 8; i++) {
        int lin4 = tid + i * 256;
        *(float4*)&ows[lin4 * 4] = *(const float4*)&ow[lin4 * 4];
    }
    if (tid < 128) {
        int n = n0 + tid;
        float m0 = g_mm[b*3+0][n], m1 = g_mm[b*3+1][n], m2 = g_mm[b*3+2][n];
        float ms = fmaxf(m0, fmaxf(m1, m2));
        float w0 = ex2(m0 - ms), w1 = ex2(m1 - ms), w2 = ex2(m2 - ms);
        float ls = g_ll[b*3+0][n]*w0 + g_ll[b*3+1][n]*w1 + g_ll[b*3+2][n]*w2;
        float inv = 1.0f / ls;
        wsc[tid]       = w0 * inv;
        wsc[128 + tid] = w1 * inv;
        wsc[256 + tid] = w2 * inv;
    }
    __syncthreads();

    #pragma unroll
    for (int i = 0; i < 16; i++) {
        int idx = tid + i * 256;       // 0..4095
        int r = idx >> 7, n = idx & 127;
        float v = g_op[b*3+0][r][n0+n] * wsc[n]
                + g_op[b*3+1][r][n0+n] * wsc[128+n]
                + g_op[b*3+2][r][n0+n] * wsc[256+n];
        oc[idx] = v;
    }
    __syncthreads();

    // out proj: thread = channel c, f32x2 over n pairs, weights in regs
    {
        u64 wd[32];
        #pragma unroll
        for (int r = 0; r < 32; r++) wd[r] = dup2(ows[tid * 32 + r]);
        #pragma unroll 2
        for (int np = 0; np < 64; np++) {
            u64 acc = 0ull;
            #pragma unroll
            for (int r = 0; r < 32; r++) {
                u64 ov = *(u64*)&oc[r * 128 + np * 2];   // broadcast LDS.64
                acc = ffma2(wd[r], ov, acc);
            }
            *(u64*)&os[tid * 128 + np * 2] = acc;
        }
    }
    __syncthreads();

    const float* xb = x + (size_t)b * CC * NN;
    float* ob = out + (size_t)b * CC * NN;
    #pragma unroll
    for (int i = 0; i < 32; i++) {
        int lin4 = tid + i * 256;      // 0..8191
        int c = lin4 >> 5, n4 = (lin4 & 31) * 4;
        float4 xv = *(const float4*)&xb[(size_t)c * NN + n0 + n4];
        float4 ov = *(float4*)&os[c * 128 + n4];
        *(float4*)&ob[(size_t)c * NN + n0 + n4] =
            make_float4(xv.x + ov.x, xv.y + ov.y, xv.z + ov.z, xv.w + ov.w);
    }
}

// ============================================================================
extern "C" void kernel_launch(void* const* d_in, const int* in_sizes, int n_in,
                              void* d_out, int out_size)
{
    const float* x  = (const float*)d_in[0];
    const float* qw = (const float*)d_in[1];
    const float* kw = (const float*)d_in[2];
    const float* vw = (const float*)d_in[3];
    const float* ow = (const float*)d_in[4];
    float* out = (float*)d_out;

    cudaFuncSetAttribute(flash_kernel,
        cudaFuncAttributeMaxDynamicSharedMemorySize, FL_SMEM_BYTES);
    cudaFuncSetAttribute(combine_kernel,
        cudaFuncAttributeMaxDynamicSharedMemorySize, K3_SMEM_BYTES);

    proj_kernel<<<dim3(NT, 3, BB), 256>>>(x, qw, kw, vw);
    flash_kernel<<<dim3(NT, JS, BB), 256, FL_SMEM_BYTES>>>();
    combine_kernel<<<dim3(NT, BB), 256, K3_SMEM_BYTES>>>(x, ow, out);
}